// round 8
// baseline (speedup 1.0000x reference)
#include <cuda_runtime.h>
#include <math.h>
#include <stdint.h>

// Problem constants
#define NB   4
#define SEQ  2048
#define DM   1024
#define NH   16
#define HD   64
#define MROWS (NB*SEQ)          // 8192

// Scratch (device globals — no allocation allowed)
__device__ float g_q  [MROWS*DM];
__device__ float g_k  [MROWS*DM];
__device__ float g_v  [MROWS*DM];
__device__ float g_att[MROWS*DM];
__device__ float g_wr [4][DM*DM];   // tf32-rounded weights (natural [k][n] layout)

__device__ __forceinline__ uint32_t tf32r(float x) {
    uint32_t u;
    asm("cvt.rna.tf32.f32 %0, %1;" : "=r"(u) : "f"(x));
    return u;
}
__device__ __forceinline__ float tf32rf(float x) {
    return __uint_as_float(tf32r(x));
}

__device__ __forceinline__ uint32_t smem_u32(const void* p) {
    uint32_t a;
    asm("{ .reg .u64 t; cvta.to.shared.u64 t, %1; cvt.u32.u64 %0, t; }"
        : "=r"(a) : "l"(p));
    return a;
}

#define CP_ASYNC16(dst, src) \
    asm volatile("cp.async.cg.shared.global [%0], [%1], 16;" \
                 :: "r"(dst), "l"(src) : "memory")
#define CP_COMMIT() asm volatile("cp.async.commit_group;" ::: "memory")
#define CP_WAIT0()  asm volatile("cp.async.wait_group 0;" ::: "memory")

#define MMA_TF32(c0, c1, c2, c3, a0, a1, a2, a3, b0, b1) \
    asm volatile("mma.sync.aligned.m16n8k8.row.col.f32.tf32.tf32.f32 " \
        "{%0,%1,%2,%3}, {%4,%5,%6,%7}, {%8,%9}, {%0,%1,%2,%3};" \
        : "+f"(c0), "+f"(c1), "+f"(c2), "+f"(c3) \
        : "r"(a0), "r"(a1), "r"(a2), "r"(a3), "r"(b0), "r"(b1))

// ---------------------------------------------------------------------------
// Weight pre-round: g_wr[i] = tf32_rna(W[i]) elementwise. Grid-stride float4.
// ---------------------------------------------------------------------------
__global__ __launch_bounds__(256) void round_w_k(
    const float* __restrict__ W0, const float* __restrict__ W1,
    const float* __restrict__ W2, const float* __restrict__ W3,
    float* __restrict__ D)
{
    const int n4 = DM * DM / 4;           // float4s per weight
    for (int i = blockIdx.x * blockDim.x + threadIdx.x; i < 4 * n4;
         i += gridDim.x * blockDim.x) {
        const int w = i / n4, j = i - w * n4;
        const float* W = (w == 0) ? W0 : (w == 1) ? W1 : (w == 2) ? W2 : W3;
        float4 v = *(const float4*)(W + 4 * (size_t)j);
        v.x = tf32rf(v.x); v.y = tf32rf(v.y);
        v.z = tf32rf(v.z); v.w = tf32rf(v.w);
        *(float4*)(D + (size_t)w * DM * DM + 4 * (size_t)j) = v;
    }
}

// ---------------------------------------------------------------------------
// Tensor-core GEMM via mma.sync (tf32), cp.async double-buffered, weights
// consumed in NATURAL [k][n] layout (pre-rounded to tf32).
//   C[M,1024] = A[M,1024] @ W[1024,1024] + bias
// roundC != 0 -> epilogue stores tf32-rounded results (for downstream MMAs).
// ---------------------------------------------------------------------------
#define LDA 36
#define LDB 136
#define GOFF_A(buf) ((buf) * (128 * LDA))                  // words
#define GOFF_B(buf) (2 * 128 * LDA + (buf) * (32 * LDB))   // words
#define GEMM_WORDS (2 * 128 * LDA + 2 * 32 * LDB)          // 17920 words
#define GEMM_SMEM  (GEMM_WORDS * 4)                        // 71680 B

__global__ __launch_bounds__(256, 2) void gemm_mma_k(
    const float* __restrict__ A0, const float* __restrict__ A1,
    const float* __restrict__ A2,
    const float* __restrict__ W0, const float* __restrict__ W1,
    const float* __restrict__ W2,
    const float* __restrict__ b0_, const float* __restrict__ b1_,
    const float* __restrict__ b2_,
    float* __restrict__ C0, float* __restrict__ C1, float* __restrict__ C2,
    int roundC)
{
    extern __shared__ uint32_t smg[];
    const uint32_t sbase = smem_u32(smg);

    const int z = blockIdx.z;
    const float* A    = (z == 0) ? A0 : (z == 1) ? A1 : A2;
    const float* W    = (z == 0) ? W0 : (z == 1) ? W1 : W2;
    const float* bias = (z == 0) ? b0_ : (z == 1) ? b1_ : b2_;
    float*       C    = (z == 0) ? C0 : (z == 1) ? C1 : C2;

    const int t    = threadIdx.x;
    const int lane = t & 31;
    const int wid  = t >> 5;
    const int m0   = blockIdx.y * 128;
    const int n0   = blockIdx.x * 128;
    const int wm   = (wid & 3) * 32;
    const int wn   = (wid >> 2) * 64;
    const int g    = lane >> 2;
    const int kq   = lane & 3;

    // cp.async mapping — A: row = ar + i*32 (i=0..3), cols ac4..ac4+3
    const int ar  = t >> 3;              // 0..31
    const int ac4 = (t & 7) << 2;        // 0..28
    // B: row = br + i*8 (i=0..3), cols bc4..bc4+3
    const int br  = t >> 5;              // 0..7
    const int bc4 = (t & 31) << 2;       // 0..124

    float acc[2][8][4];
    #pragma unroll
    for (int mi = 0; mi < 2; mi++)
        #pragma unroll
        for (int nj = 0; nj < 8; nj++)
            #pragma unroll
            for (int r = 0; r < 4; r++) acc[mi][nj][r] = 0.f;

    // ---- Prologue: issue chunk 0 ----
    {
        const float* ap = A + (size_t)(m0 + ar) * DM + ac4;
        #pragma unroll
        for (int i = 0; i < 4; i++)
            CP_ASYNC16(sbase + (GOFF_A(0) + (ar + i * 32) * LDA + ac4) * 4,
                       ap + (size_t)(i * 32) * DM);
        const float* wp = W + (size_t)br * DM + n0 + bc4;
        #pragma unroll
        for (int i = 0; i < 4; i++)
            CP_ASYNC16(sbase + (GOFF_B(0) + (br + i * 8) * LDB + bc4) * 4,
                       wp + (size_t)(i * 8) * DM);
        CP_COMMIT();
    }

    #pragma unroll 1
    for (int kt = 0; kt < 32; kt++) {
        const int cur = kt & 1;
        const int nxt = cur ^ 1;

        CP_WAIT0();
        __syncthreads();

        if (kt + 1 < 32) {
            const int kf = (kt + 1) * 32;
            const float* ap = A + (size_t)(m0 + ar) * DM + kf + ac4;
            #pragma unroll
            for (int i = 0; i < 4; i++)
                CP_ASYNC16(sbase + (GOFF_A(nxt) + (ar + i * 32) * LDA + ac4) * 4,
                           ap + (size_t)(i * 32) * DM);
            const float* wp = W + (size_t)(kf + br) * DM + n0 + bc4;
            #pragma unroll
            for (int i = 0; i < 4; i++)
                CP_ASYNC16(sbase + (GOFF_B(nxt) + (br + i * 8) * LDB + bc4) * 4,
                           wp + (size_t)(i * 8) * DM);
            CP_COMMIT();
        }

        const uint32_t* As = smg + GOFF_A(cur);
        const uint32_t* Bs = smg + GOFF_B(cur);

        #pragma unroll
        for (int ks = 0; ks < 4; ks++) {
            const int k0 = ks * 8 + kq;
            uint32_t af[2][4];
            #pragma unroll
            for (int mi = 0; mi < 2; mi++) {
                const int row = wm + mi * 16 + g;
                af[mi][0] = As[row * LDA + k0];
                af[mi][1] = As[(row + 8) * LDA + k0];
                af[mi][2] = As[row * LDA + k0 + 4];
                af[mi][3] = As[(row + 8) * LDA + k0 + 4];
            }
            #pragma unroll
            for (int nj = 0; nj < 8; nj++) {
                const int col = wn + nj * 8 + g;
                uint32_t bb0 = Bs[k0 * LDB + col];
                uint32_t bb1 = Bs[(k0 + 4) * LDB + col];
                #pragma unroll
                for (int mi = 0; mi < 2; mi++)
                    MMA_TF32(acc[mi][nj][0], acc[mi][nj][1],
                             acc[mi][nj][2], acc[mi][nj][3],
                             af[mi][0], af[mi][1], af[mi][2], af[mi][3],
                             bb0, bb1);
            }
        }
    }

    #pragma unroll
    for (int mi = 0; mi < 2; mi++) {
        const int row = m0 + wm + mi * 16 + g;
        #pragma unroll
        for (int nj = 0; nj < 8; nj++) {
            const int col = n0 + wn + nj * 8 + kq * 2;
            const float bx = bias[col], by = bias[col + 1];
            float2 v0 = make_float2(acc[mi][nj][0] + bx, acc[mi][nj][1] + by);
            float2 v1 = make_float2(acc[mi][nj][2] + bx, acc[mi][nj][3] + by);
            if (roundC) {
                v0.x = tf32rf(v0.x); v0.y = tf32rf(v0.y);
                v1.x = tf32rf(v1.x); v1.y = tf32rf(v1.y);
            }
            *(float2*)(C + (size_t)row * DM + col)       = v0;
            *(float2*)(C + (size_t)(row + 8) * DM + col) = v1;
        }
    }
}

// ---------------------------------------------------------------------------
// Tensor-core flash attention (tf32 mma.sync) with cp.async double buffering.
// K/V arrive tf32-exact (rounded in the QKV GEMM epilogue), so raw cp.async +
// MMA truncation is lossless. Output rounded to tf32 for the output GEMM.
// ---------------------------------------------------------------------------
#define KST 68
#define VST 72
#define OFF_KS(buf) ((buf) * 4352)
#define OFF_VS(buf) (8704 + (buf) * 4608)
#define OFF_MADD(buf) (17920 + (buf) * 64)
#define OFF_PS 18048
#define ATT_WORDS (OFF_PS + 128 * KST)        // 26752 words
#define ATT_SMEM  (ATT_WORDS * 4)             // 107008 B

__global__ __launch_bounds__(256, 2) void attn_mma_k(
    const float* __restrict__ q, const float* __restrict__ k,
    const float* __restrict__ v, const int* __restrict__ mask,
    float* __restrict__ o)
{
    extern __shared__ uint32_t smu[];
    uint32_t* Ps = smu + OFF_PS;
    const uint32_t sbase = smem_u32(smu);

    const int t    = threadIdx.x;
    const int lane = t & 31;
    const int wid  = t >> 5;
    const int g    = lane >> 2;
    const int kq   = lane & 3;
    const int bh   = blockIdx.x;
    const int b    = bh >> 4;
    const int h    = bh & 15;
    const int qt   = blockIdx.y;

    const int qbase = b * SEQ + qt * 128;
    const int kbase = b * SEQ;
    const int hcol  = h * HD;
    const int wr    = wid * 16;

    const int crow = t >> 4;
    const int cc4  = (t & 15) << 2;

    #pragma unroll
    for (int it = 0; it < 8; it++) {
        int idx = it * 256 + t;
        int r = idx >> 4, c4 = (idx & 15) << 2;
        float4 qv = *(const float4*)(q + (size_t)(qbase + r) * DM + hcol + c4);
        uint32_t* p = &Ps[r * KST + c4];
        p[0] = tf32r(qv.x * 0.125f); p[1] = tf32r(qv.y * 0.125f);
        p[2] = tf32r(qv.z * 0.125f); p[3] = tf32r(qv.w * 0.125f);
    }

    {
        const float* kp = k + (size_t)(kbase + crow) * DM + hcol + cc4;
        const float* vp = v + (size_t)(kbase + crow) * DM + hcol + cc4;
        #pragma unroll
        for (int it = 0; it < 4; it++) {
            const int r = crow + it * 16;
            CP_ASYNC16(sbase + (OFF_KS(0) + r * KST + cc4) * 4, kp + (size_t)(it * 16) * DM);
            CP_ASYNC16(sbase + (OFF_VS(0) + r * VST + cc4) * 4, vp + (size_t)(it * 16) * DM);
        }
        CP_COMMIT();
    }
    if (t < 64) {
        ((float*)(smu + OFF_MADD(0)))[t] = mask[b * SEQ + t] ? 0.f : -1e9f;
    }
    int mreg = (t < 64) ? mask[b * SEQ + 64 + t] : 0;

    __syncthreads();

    uint32_t qf[8][4];
    #pragma unroll
    for (int ks = 0; ks < 8; ks++) {
        const int k0 = ks * 8 + kq;
        qf[ks][0] = Ps[(wr + g) * KST + k0];
        qf[ks][1] = Ps[(wr + g + 8) * KST + k0];
        qf[ks][2] = Ps[(wr + g) * KST + k0 + 4];
        qf[ks][3] = Ps[(wr + g + 8) * KST + k0 + 4];
    }

    float m0 = -1e30f, m1 = -1e30f, l0 = 0.f, l1 = 0.f;
    float acc[8][4];
    #pragma unroll
    for (int nt = 0; nt < 8; nt++)
        #pragma unroll
        for (int j = 0; j < 4; j++) acc[nt][j] = 0.f;

    #pragma unroll 1
    for (int kt = 0; kt < 32; kt++) {
        const int cur = kt & 1;
        const int nxt = cur ^ 1;

        CP_WAIT0();
        __syncthreads();

        if (kt + 1 < 32) {
            const size_t rb = (size_t)(kbase + (kt + 1) * 64 + crow) * DM + hcol + cc4;
            const float* kp = k + rb;
            const float* vp = v + rb;
            #pragma unroll
            for (int it = 0; it < 4; it++) {
                const int r = crow + it * 16;
                CP_ASYNC16(sbase + (OFF_KS(nxt) + r * KST + cc4) * 4, kp + (size_t)(it * 16) * DM);
                CP_ASYNC16(sbase + (OFF_VS(nxt) + r * VST + cc4) * 4, vp + (size_t)(it * 16) * DM);
            }
            CP_COMMIT();
            if (t < 64) {
                ((float*)(smu + OFF_MADD(nxt)))[t] = mreg ? 0.f : -1e9f;
                if (kt + 2 < 32) mreg = mask[b * SEQ + (kt + 2) * 64 + t];
            }
        }

        const uint32_t* Ks = smu + OFF_KS(cur);
        const uint32_t* Vs = smu + OFF_VS(cur);
        const float* madd  = (const float*)(smu + OFF_MADD(cur));

        float s[8][4];
        #pragma unroll
        for (int nt = 0; nt < 8; nt++)
            #pragma unroll
            for (int j = 0; j < 4; j++) s[nt][j] = 0.f;

        #pragma unroll
        for (int ks = 0; ks < 8; ks++) {
            const int k0 = ks * 8 + kq;
            #pragma unroll
            for (int nt = 0; nt < 8; nt++) {
                uint32_t bb0 = Ks[(nt * 8 + g) * KST + k0];
                uint32_t bb1 = Ks[(nt * 8 + g) * KST + k0 + 4];
                MMA_TF32(s[nt][0], s[nt][1], s[nt][2], s[nt][3],
                         qf[ks][0], qf[ks][1], qf[ks][2], qf[ks][3], bb0, bb1);
            }
        }

        float rmax0 = -1e30f, rmax1 = -1e30f;
        #pragma unroll
        for (int nt = 0; nt < 8; nt++) {
            float2 md = *(float2*)&madd[nt * 8 + 2 * kq];
            s[nt][0] += md.x; s[nt][1] += md.y;
            s[nt][2] += md.x; s[nt][3] += md.y;
            rmax0 = fmaxf(rmax0, fmaxf(s[nt][0], s[nt][1]));
            rmax1 = fmaxf(rmax1, fmaxf(s[nt][2], s[nt][3]));
        }
        rmax0 = fmaxf(rmax0, __shfl_xor_sync(0xffffffffu, rmax0, 1));
        rmax0 = fmaxf(rmax0, __shfl_xor_sync(0xffffffffu, rmax0, 2));
        rmax1 = fmaxf(rmax1, __shfl_xor_sync(0xffffffffu, rmax1, 1));
        rmax1 = fmaxf(rmax1, __shfl_xor_sync(0xffffffffu, rmax1, 2));

        const float mn0 = fmaxf(m0, rmax0);
        const float mn1 = fmaxf(m1, rmax1);
        const float a0  = __expf(m0 - mn0);
        const float a1  = __expf(m1 - mn1);
        float sum0 = 0.f, sum1 = 0.f;

        #pragma unroll
        for (int nt = 0; nt < 8; nt++) {
            float p0 = __expf(s[nt][0] - mn0);
            float p1 = __expf(s[nt][1] - mn0);
            float p2 = __expf(s[nt][2] - mn1);
            float p3 = __expf(s[nt][3] - mn1);
            sum0 += p0 + p1;
            sum1 += p2 + p3;
            uint2 w0 = make_uint2(tf32r(p0), tf32r(p1));
            uint2 w1 = make_uint2(tf32r(p2), tf32r(p3));
            *(uint2*)&Ps[(wr + g) * KST + nt * 8 + 2 * kq]     = w0;
            *(uint2*)&Ps[(wr + g + 8) * KST + nt * 8 + 2 * kq] = w1;
        }
        sum0 += __shfl_xor_sync(0xffffffffu, sum0, 1);
        sum0 += __shfl_xor_sync(0xffffffffu, sum0, 2);
        sum1 += __shfl_xor_sync(0xffffffffu, sum1, 1);
        sum1 += __shfl_xor_sync(0xffffffffu, sum1, 2);

        l0 = l0 * a0 + sum0;  m0 = mn0;
        l1 = l1 * a1 + sum1;  m1 = mn1;
        #pragma unroll
        for (int nt = 0; nt < 8; nt++) {
            acc[nt][0] *= a0; acc[nt][1] *= a0;
            acc[nt][2] *= a1; acc[nt][3] *= a1;
        }
        __syncwarp();

        #pragma unroll
        for (int ks = 0; ks < 8; ks++) {
            const int k0 = ks * 8 + kq;
            uint32_t pa0 = Ps[(wr + g) * KST + k0];
            uint32_t pa1 = Ps[(wr + g + 8) * KST + k0];
            uint32_t pa2 = Ps[(wr + g) * KST + k0 + 4];
            uint32_t pa3 = Ps[(wr + g + 8) * KST + k0 + 4];
            #pragma unroll
            for (int nt = 0; nt < 8; nt++) {
                uint32_t bb0 = Vs[(k0) * VST + nt * 8 + g];
                uint32_t bb1 = Vs[(k0 + 4) * VST + nt * 8 + g];
                MMA_TF32(acc[nt][0], acc[nt][1], acc[nt][2], acc[nt][3],
                         pa0, pa1, pa2, pa3, bb0, bb1);
            }
        }
    }

    const float inv0 = (l0 > 0.f) ? 1.f / l0 : 0.f;
    const float inv1 = (l1 > 0.f) ? 1.f / l1 : 0.f;
    const int row0 = qbase + wr + g;
    #pragma unroll
    for (int nt = 0; nt < 8; nt++) {
        const int col = hcol + nt * 8 + 2 * kq;
        float2 o0 = make_float2(tf32rf(acc[nt][0] * inv0), tf32rf(acc[nt][1] * inv0));
        float2 o1 = make_float2(tf32rf(acc[nt][2] * inv1), tf32rf(acc[nt][3] * inv1));
        *(float2*)(o + (size_t)row0 * DM + col)       = o0;
        *(float2*)(o + (size_t)(row0 + 8) * DM + col) = o1;
    }
}

// ---------------------------------------------------------------------------
// Launch: weight pre-round -> QKV GEMMs (fused, rounded out) -> attention
// (rounded out) -> output GEMM (raw fp32 out).
// ---------------------------------------------------------------------------
extern "C" void kernel_launch(void* const* d_in, const int* in_sizes, int n_in,
                              void* d_out, int out_size)
{
    const float* Q    = (const float*)d_in[0];
    const float* K    = (const float*)d_in[1];
    const float* V    = (const float*)d_in[2];
    const int*   mask = (const int*)  d_in[3];
    const float* Wq   = (const float*)d_in[4];
    const float* bq   = (const float*)d_in[5];
    const float* Wk   = (const float*)d_in[6];
    const float* bk   = (const float*)d_in[7];
    const float* Wv   = (const float*)d_in[8];
    const float* bv   = (const float*)d_in[9];
    const float* Wo   = (const float*)d_in[10];
    const float* bo   = (const float*)d_in[11];
    float* out = (float*)d_out;

    float *gq, *gk, *gv, *ga, *gwr;
    cudaGetSymbolAddress((void**)&gq,  g_q);
    cudaGetSymbolAddress((void**)&gk,  g_k);
    cudaGetSymbolAddress((void**)&gv,  g_v);
    cudaGetSymbolAddress((void**)&ga,  g_att);
    cudaGetSymbolAddress((void**)&gwr, g_wr);
    float* wrq = gwr + 0 * (size_t)DM * DM;
    float* wrk = gwr + 1 * (size_t)DM * DM;
    float* wrv = gwr + 2 * (size_t)DM * DM;
    float* wro = gwr + 3 * (size_t)DM * DM;

    cudaFuncSetAttribute(gemm_mma_k, cudaFuncAttributeMaxDynamicSharedMemorySize,
                         GEMM_SMEM);
    cudaFuncSetAttribute(attn_mma_k, cudaFuncAttributeMaxDynamicSharedMemorySize,
                         ATT_SMEM);

    round_w_k<<<1184, 256>>>(Wq, Wk, Wv, Wo, gwr);

    dim3 qkv_grid(DM / 128, MROWS / 128, 3);  // (8, 64, 3)
    dim3 out_grid(DM / 128, MROWS / 128, 1);  // (8, 64, 1)
    dim3 attn_grid(NB * NH, SEQ / 128);       // (64, 16)

    gemm_mma_k<<<qkv_grid, 256, GEMM_SMEM>>>(Q, K, V, wrq, wrk, wrv,
                                             bq, bk, bv, gq, gk, gv, 1);
    attn_mma_k<<<attn_grid, 256, ATT_SMEM>>>(gq, gk, gv, mask, ga);
    gemm_mma_k<<<out_grid, 256, GEMM_SMEM>>>(ga, ga, ga, wro, wro, wro,
                                             bo, bo, bo, out, out, out, 0);
}

// round 9
// speedup vs baseline: 1.0347x; 1.0347x over previous
#include <cuda_runtime.h>
#include <math.h>
#include <stdint.h>

// Problem constants
#define NB   4
#define SEQ  2048
#define DM   1024
#define NH   16
#define HD   64
#define MROWS (NB*SEQ)          // 8192

// Scratch (device globals — no allocation allowed)
__device__ float g_q  [MROWS*DM];
__device__ float g_k  [MROWS*DM];
__device__ float g_v  [MROWS*DM];
__device__ float g_att[MROWS*DM];
__device__ float g_wr [4][DM*DM];   // tf32-rounded weights (natural [k][n] layout)

__device__ __forceinline__ uint32_t tf32r(float x) {
    uint32_t u;
    asm("cvt.rna.tf32.f32 %0, %1;" : "=r"(u) : "f"(x));
    return u;
}
__device__ __forceinline__ float tf32rf(float x) {
    return __uint_as_float(tf32r(x));
}

__device__ __forceinline__ uint32_t smem_u32(const void* p) {
    uint32_t a;
    asm("{ .reg .u64 t; cvta.to.shared.u64 t, %1; cvt.u32.u64 %0, t; }"
        : "=r"(a) : "l"(p));
    return a;
}

#define CP_ASYNC16(dst, src) \
    asm volatile("cp.async.cg.shared.global [%0], [%1], 16;" \
                 :: "r"(dst), "l"(src) : "memory")
#define CP_COMMIT() asm volatile("cp.async.commit_group;" ::: "memory")
#define CP_WAIT0()  asm volatile("cp.async.wait_group 0;" ::: "memory")

#define MMA_TF32(c0, c1, c2, c3, a0, a1, a2, a3, b0, b1) \
    asm volatile("mma.sync.aligned.m16n8k8.row.col.f32.tf32.tf32.f32 " \
        "{%0,%1,%2,%3}, {%4,%5,%6,%7}, {%8,%9}, {%0,%1,%2,%3};" \
        : "+f"(c0), "+f"(c1), "+f"(c2), "+f"(c3) \
        : "r"(a0), "r"(a1), "r"(a2), "r"(a3), "r"(b0), "r"(b1))

// ---------------------------------------------------------------------------
// Weight pre-round: g_wr[i] = tf32_rna(W[i]) elementwise.
// ---------------------------------------------------------------------------
__global__ __launch_bounds__(256) void round_w_k(
    const float* __restrict__ W0, const float* __restrict__ W1,
    const float* __restrict__ W2, const float* __restrict__ W3,
    float* __restrict__ D)
{
    const int n4 = DM * DM / 4;
    for (int i = blockIdx.x * blockDim.x + threadIdx.x; i < 4 * n4;
         i += gridDim.x * blockDim.x) {
        const int w = i / n4, j = i - w * n4;
        const float* W = (w == 0) ? W0 : (w == 1) ? W1 : (w == 2) ? W2 : W3;
        float4 v = *(const float4*)(W + 4 * (size_t)j);
        v.x = tf32rf(v.x); v.y = tf32rf(v.y);
        v.z = tf32rf(v.z); v.w = tf32rf(v.w);
        *(float4*)(D + (size_t)w * DM * DM + 4 * (size_t)j) = v;
    }
}

// ---------------------------------------------------------------------------
// Tensor-core GEMM (tf32 mma.sync), cp.async double-buffered.
// 128 threads = 4 warps (2m x 2n), warp tile 64x64 (mi=4), CTA tile 128x128.
// Per chunk per warp: 128 LDS : 128 MMA (ratio 1.0).
//   As[2][128][36] : A chunk [m][k]  (A-frags: bank 4g+kq, CF)
//   Bs[2][32][136] : W chunk [k][n]  (B-frags: bank 8kq+g, CF)
// ---------------------------------------------------------------------------
#define LDA 36
#define LDB 136
#define GOFF_A(buf) ((buf) * (128 * LDA))
#define GOFF_B(buf) (2 * 128 * LDA + (buf) * (32 * LDB))
#define GEMM_WORDS (2 * 128 * LDA + 2 * 32 * LDB)          // 17920 words
#define GEMM_SMEM  (GEMM_WORDS * 4)                        // 71680 B

__global__ __launch_bounds__(128, 2) void gemm_mma_k(
    const float* __restrict__ A0, const float* __restrict__ A1,
    const float* __restrict__ A2,
    const float* __restrict__ W0, const float* __restrict__ W1,
    const float* __restrict__ W2,
    const float* __restrict__ b0_, const float* __restrict__ b1_,
    const float* __restrict__ b2_,
    float* __restrict__ C0, float* __restrict__ C1, float* __restrict__ C2,
    int roundC)
{
    extern __shared__ uint32_t smg[];
    const uint32_t sbase = smem_u32(smg);

    const int z = blockIdx.z;
    const float* A    = (z == 0) ? A0 : (z == 1) ? A1 : A2;
    const float* W    = (z == 0) ? W0 : (z == 1) ? W1 : W2;
    const float* bias = (z == 0) ? b0_ : (z == 1) ? b1_ : b2_;
    float*       C    = (z == 0) ? C0 : (z == 1) ? C1 : C2;

    const int t    = threadIdx.x;
    const int lane = t & 31;
    const int wid  = t >> 5;           // 0..3
    const int m0   = blockIdx.y * 128;
    const int n0   = blockIdx.x * 128;
    const int wm   = (wid & 1) * 64;   // warp m offset
    const int wn   = (wid >> 1) * 64;  // warp n offset
    const int g    = lane >> 2;
    const int kq   = lane & 3;

    // cp.async mapping — A: rows ar + i*16 (i=0..7), cols ac4..ac4+3
    const int ar  = t >> 3;            // 0..15
    const int ac4 = (t & 7) << 2;      // 0..28
    // B: rows br + i*4 (i=0..7), cols bc4..bc4+3
    const int br  = t >> 5;            // 0..3
    const int bc4 = (t & 31) << 2;     // 0..124

    float acc[4][8][4];
    #pragma unroll
    for (int mi = 0; mi < 4; mi++)
        #pragma unroll
        for (int nj = 0; nj < 8; nj++)
            #pragma unroll
            for (int r = 0; r < 4; r++) acc[mi][nj][r] = 0.f;

    // ---- Prologue: issue chunk 0 ----
    {
        const float* ap = A + (size_t)(m0 + ar) * DM + ac4;
        #pragma unroll
        for (int i = 0; i < 8; i++)
            CP_ASYNC16(sbase + (GOFF_A(0) + (ar + i * 16) * LDA + ac4) * 4,
                       ap + (size_t)(i * 16) * DM);
        const float* wp = W + (size_t)br * DM + n0 + bc4;
        #pragma unroll
        for (int i = 0; i < 8; i++)
            CP_ASYNC16(sbase + (GOFF_B(0) + (br + i * 4) * LDB + bc4) * 4,
                       wp + (size_t)(i * 4) * DM);
        CP_COMMIT();
    }

    #pragma unroll 1
    for (int kt = 0; kt < 32; kt++) {
        const int cur = kt & 1;
        const int nxt = cur ^ 1;

        CP_WAIT0();
        __syncthreads();

        if (kt + 1 < 32) {
            const int kf = (kt + 1) * 32;
            const float* ap = A + (size_t)(m0 + ar) * DM + kf + ac4;
            #pragma unroll
            for (int i = 0; i < 8; i++)
                CP_ASYNC16(sbase + (GOFF_A(nxt) + (ar + i * 16) * LDA + ac4) * 4,
                           ap + (size_t)(i * 16) * DM);
            const float* wp = W + (size_t)(kf + br) * DM + n0 + bc4;
            #pragma unroll
            for (int i = 0; i < 8; i++)
                CP_ASYNC16(sbase + (GOFF_B(nxt) + (br + i * 4) * LDB + bc4) * 4,
                           wp + (size_t)(i * 4) * DM);
            CP_COMMIT();
        }

        const uint32_t* As = smg + GOFF_A(cur);
        const uint32_t* Bs = smg + GOFF_B(cur);

        #pragma unroll
        for (int ks = 0; ks < 4; ks++) {
            const int k0 = ks * 8 + kq;
            uint32_t af[4][4];
            #pragma unroll
            for (int mi = 0; mi < 4; mi++) {
                const int row = wm + mi * 16 + g;
                af[mi][0] = As[row * LDA + k0];
                af[mi][1] = As[(row + 8) * LDA + k0];
                af[mi][2] = As[row * LDA + k0 + 4];
                af[mi][3] = As[(row + 8) * LDA + k0 + 4];
            }
            #pragma unroll
            for (int nj = 0; nj < 8; nj++) {
                const int col = wn + nj * 8 + g;
                uint32_t bb0 = Bs[k0 * LDB + col];
                uint32_t bb1 = Bs[(k0 + 4) * LDB + col];
                #pragma unroll
                for (int mi = 0; mi < 4; mi++)
                    MMA_TF32(acc[mi][nj][0], acc[mi][nj][1],
                             acc[mi][nj][2], acc[mi][nj][3],
                             af[mi][0], af[mi][1], af[mi][2], af[mi][3],
                             bb0, bb1);
            }
        }
    }

    #pragma unroll
    for (int mi = 0; mi < 4; mi++) {
        const int row = m0 + wm + mi * 16 + g;
        #pragma unroll
        for (int nj = 0; nj < 8; nj++) {
            const int col = n0 + wn + nj * 8 + kq * 2;
            const float bx = bias[col], by = bias[col + 1];
            float2 v0 = make_float2(acc[mi][nj][0] + bx, acc[mi][nj][1] + by);
            float2 v1 = make_float2(acc[mi][nj][2] + bx, acc[mi][nj][3] + by);
            if (roundC) {
                v0.x = tf32rf(v0.x); v0.y = tf32rf(v0.y);
                v1.x = tf32rf(v1.x); v1.y = tf32rf(v1.y);
            }
            *(float2*)(C + (size_t)row * DM + col)       = v0;
            *(float2*)(C + (size_t)(row + 8) * DM + col) = v1;
        }
    }
}

// ---------------------------------------------------------------------------
// Tensor-core flash attention (tf32 mma.sync), cp.async double-buffered.
// 128 threads = 4 warps; warp owns 32 q rows (mi=2), 64-key chunks.
// Per chunk per warp: 320 LDS : 256 MMA (was 2.25:1, now 1.25:1).
// ---------------------------------------------------------------------------
#define KST 68
#define VST 72
#define OFF_KS(buf) ((buf) * 4352)
#define OFF_VS(buf) (8704 + (buf) * 4608)
#define OFF_MADD(buf) (17920 + (buf) * 64)
#define OFF_PS 18048
#define ATT_WORDS (OFF_PS + 128 * KST)        // 26752 words
#define ATT_SMEM  (ATT_WORDS * 4)             // 107008 B

__global__ __launch_bounds__(128, 2) void attn_mma_k(
    const float* __restrict__ q, const float* __restrict__ k,
    const float* __restrict__ v, const int* __restrict__ mask,
    float* __restrict__ o)
{
    extern __shared__ uint32_t smu[];
    uint32_t* Ps = smu + OFF_PS;
    const uint32_t sbase = smem_u32(smu);

    const int t    = threadIdx.x;
    const int lane = t & 31;
    const int wid  = t >> 5;           // 0..3
    const int g    = lane >> 2;
    const int kq   = lane & 3;
    const int bh   = blockIdx.x;
    const int b    = bh >> 4;
    const int h    = bh & 15;
    const int qt   = blockIdx.y;

    const int qbase = b * SEQ + qt * 128;
    const int kbase = b * SEQ;
    const int hcol  = h * HD;
    const int wr    = wid * 32;        // warp's first q row (32 rows)

    const int crow = t >> 4;           // 0..7
    const int cc4  = (t & 15) << 2;

    // ---- Stage Q tile (scaled by 1/8, tf32-rounded) into Ps ----
    #pragma unroll
    for (int it = 0; it < 16; it++) {
        int idx = it * 128 + t;
        int r = idx >> 4, c4 = (idx & 15) << 2;
        float4 qv = *(const float4*)(q + (size_t)(qbase + r) * DM + hcol + c4);
        uint32_t* p = &Ps[r * KST + c4];
        p[0] = tf32r(qv.x * 0.125f); p[1] = tf32r(qv.y * 0.125f);
        p[2] = tf32r(qv.z * 0.125f); p[3] = tf32r(qv.w * 0.125f);
    }

    // ---- Issue cp.async for chunk 0 ----
    {
        const float* kp = k + (size_t)(kbase + crow) * DM + hcol + cc4;
        const float* vp = v + (size_t)(kbase + crow) * DM + hcol + cc4;
        #pragma unroll
        for (int it = 0; it < 8; it++) {
            const int r = crow + it * 8;
            CP_ASYNC16(sbase + (OFF_KS(0) + r * KST + cc4) * 4, kp + (size_t)(it * 8) * DM);
            CP_ASYNC16(sbase + (OFF_VS(0) + r * VST + cc4) * 4, vp + (size_t)(it * 8) * DM);
        }
        CP_COMMIT();
    }
    if (t < 64) {
        ((float*)(smu + OFF_MADD(0)))[t] = mask[b * SEQ + t] ? 0.f : -1e9f;
    }
    int mreg = (t < 64) ? mask[b * SEQ + 64 + t] : 0;

    __syncthreads();

    // Q A-fragments for both 16-row tiles, register-resident
    uint32_t qf[2][8][4];
    #pragma unroll
    for (int mi = 0; mi < 2; mi++)
        #pragma unroll
        for (int ks = 0; ks < 8; ks++) {
            const int k0 = ks * 8 + kq;
            const int row = wr + mi * 16 + g;
            qf[mi][ks][0] = Ps[row * KST + k0];
            qf[mi][ks][1] = Ps[(row + 8) * KST + k0];
            qf[mi][ks][2] = Ps[row * KST + k0 + 4];
            qf[mi][ks][3] = Ps[(row + 8) * KST + k0 + 4];
        }

    float mx[2][2], lx[2][2];
    #pragma unroll
    for (int mi = 0; mi < 2; mi++) {
        mx[mi][0] = -1e30f; mx[mi][1] = -1e30f;
        lx[mi][0] = 0.f;    lx[mi][1] = 0.f;
    }
    float acc[2][8][4];
    #pragma unroll
    for (int mi = 0; mi < 2; mi++)
        #pragma unroll
        for (int nt = 0; nt < 8; nt++)
            #pragma unroll
            for (int j = 0; j < 4; j++) acc[mi][nt][j] = 0.f;

    #pragma unroll 1
    for (int kt = 0; kt < 32; kt++) {
        const int cur = kt & 1;
        const int nxt = cur ^ 1;

        CP_WAIT0();
        __syncthreads();

        if (kt + 1 < 32) {
            const size_t rb = (size_t)(kbase + (kt + 1) * 64 + crow) * DM + hcol + cc4;
            const float* kp = k + rb;
            const float* vp = v + rb;
            #pragma unroll
            for (int it = 0; it < 8; it++) {
                const int r = crow + it * 8;
                CP_ASYNC16(sbase + (OFF_KS(nxt) + r * KST + cc4) * 4, kp + (size_t)(it * 8) * DM);
                CP_ASYNC16(sbase + (OFF_VS(nxt) + r * VST + cc4) * 4, vp + (size_t)(it * 8) * DM);
            }
            CP_COMMIT();
            if (t < 64) {
                ((float*)(smu + OFF_MADD(nxt)))[t] = mreg ? 0.f : -1e9f;
                if (kt + 2 < 32) mreg = mask[b * SEQ + (kt + 2) * 64 + t];
            }
        }

        const uint32_t* Ks = smu + OFF_KS(cur);
        const uint32_t* Vs = smu + OFF_VS(cur);
        const float* madd  = (const float*)(smu + OFF_MADD(cur));

        // ---- S = (Q/8) K^T ----
        float s[2][8][4];
        #pragma unroll
        for (int mi = 0; mi < 2; mi++)
            #pragma unroll
            for (int nt = 0; nt < 8; nt++)
                #pragma unroll
                for (int j = 0; j < 4; j++) s[mi][nt][j] = 0.f;

        #pragma unroll
        for (int ks = 0; ks < 8; ks++) {
            const int k0 = ks * 8 + kq;
            #pragma unroll
            for (int nt = 0; nt < 8; nt++) {
                uint32_t bb0 = Ks[(nt * 8 + g) * KST + k0];
                uint32_t bb1 = Ks[(nt * 8 + g) * KST + k0 + 4];
                #pragma unroll
                for (int mi = 0; mi < 2; mi++)
                    MMA_TF32(s[mi][nt][0], s[mi][nt][1], s[mi][nt][2], s[mi][nt][3],
                             qf[mi][ks][0], qf[mi][ks][1],
                             qf[mi][ks][2], qf[mi][ks][3], bb0, bb1);
            }
        }

        // ---- Online softmax per mi (rows g, g+8; cols in-warp) ----
        #pragma unroll
        for (int mi = 0; mi < 2; mi++) {
            float rmax0 = -1e30f, rmax1 = -1e30f;
            #pragma unroll
            for (int nt = 0; nt < 8; nt++) {
                float2 md = *(float2*)&madd[nt * 8 + 2 * kq];
                s[mi][nt][0] += md.x; s[mi][nt][1] += md.y;
                s[mi][nt][2] += md.x; s[mi][nt][3] += md.y;
                rmax0 = fmaxf(rmax0, fmaxf(s[mi][nt][0], s[mi][nt][1]));
                rmax1 = fmaxf(rmax1, fmaxf(s[mi][nt][2], s[mi][nt][3]));
            }
            rmax0 = fmaxf(rmax0, __shfl_xor_sync(0xffffffffu, rmax0, 1));
            rmax0 = fmaxf(rmax0, __shfl_xor_sync(0xffffffffu, rmax0, 2));
            rmax1 = fmaxf(rmax1, __shfl_xor_sync(0xffffffffu, rmax1, 1));
            rmax1 = fmaxf(rmax1, __shfl_xor_sync(0xffffffffu, rmax1, 2));

            const float mn0 = fmaxf(mx[mi][0], rmax0);
            const float mn1 = fmaxf(mx[mi][1], rmax1);
            const float a0  = __expf(mx[mi][0] - mn0);
            const float a1  = __expf(mx[mi][1] - mn1);
            float sum0 = 0.f, sum1 = 0.f;

            const int row = wr + mi * 16 + g;
            #pragma unroll
            for (int nt = 0; nt < 8; nt++) {
                float p0 = __expf(s[mi][nt][0] - mn0);
                float p1 = __expf(s[mi][nt][1] - mn0);
                float p2 = __expf(s[mi][nt][2] - mn1);
                float p3 = __expf(s[mi][nt][3] - mn1);
                sum0 += p0 + p1;
                sum1 += p2 + p3;
                uint2 w0 = make_uint2(tf32r(p0), tf32r(p1));
                uint2 w1 = make_uint2(tf32r(p2), tf32r(p3));
                *(uint2*)&Ps[row * KST + nt * 8 + 2 * kq]       = w0;
                *(uint2*)&Ps[(row + 8) * KST + nt * 8 + 2 * kq] = w1;
            }
            sum0 += __shfl_xor_sync(0xffffffffu, sum0, 1);
            sum0 += __shfl_xor_sync(0xffffffffu, sum0, 2);
            sum1 += __shfl_xor_sync(0xffffffffu, sum1, 1);
            sum1 += __shfl_xor_sync(0xffffffffu, sum1, 2);

            lx[mi][0] = lx[mi][0] * a0 + sum0;  mx[mi][0] = mn0;
            lx[mi][1] = lx[mi][1] * a1 + sum1;  mx[mi][1] = mn1;
            #pragma unroll
            for (int nt = 0; nt < 8; nt++) {
                acc[mi][nt][0] *= a0; acc[mi][nt][1] *= a0;
                acc[mi][nt][2] *= a1; acc[mi][nt][3] *= a1;
            }
        }
        __syncwarp();   // P stores visible to own-warp LDS

        // ---- O += P V ----
        #pragma unroll
        for (int ks = 0; ks < 8; ks++) {
            const int k0 = ks * 8 + kq;
            uint32_t pa[2][4];
            #pragma unroll
            for (int mi = 0; mi < 2; mi++) {
                const int row = wr + mi * 16 + g;
                pa[mi][0] = Ps[row * KST + k0];
                pa[mi][1] = Ps[(row + 8) * KST + k0];
                pa[mi][2] = Ps[row * KST + k0 + 4];
                pa[mi][3] = Ps[(row + 8) * KST + k0 + 4];
            }
            #pragma unroll
            for (int nt = 0; nt < 8; nt++) {
                uint32_t bb0 = Vs[(k0) * VST + nt * 8 + g];
                uint32_t bb1 = Vs[(k0 + 4) * VST + nt * 8 + g];
                #pragma unroll
                for (int mi = 0; mi < 2; mi++)
                    MMA_TF32(acc[mi][nt][0], acc[mi][nt][1],
                             acc[mi][nt][2], acc[mi][nt][3],
                             pa[mi][0], pa[mi][1], pa[mi][2], pa[mi][3],
                             bb0, bb1);
            }
        }
    }

    // ---- Finalize (tf32-rounded for the output GEMM) ----
    #pragma unroll
    for (int mi = 0; mi < 2; mi++) {
        const float inv0 = (lx[mi][0] > 0.f) ? 1.f / lx[mi][0] : 0.f;
        const float inv1 = (lx[mi][1] > 0.f) ? 1.f / lx[mi][1] : 0.f;
        const int row0 = qbase + wr + mi * 16 + g;
        #pragma unroll
        for (int nt = 0; nt < 8; nt++) {
            const int col = hcol + nt * 8 + 2 * kq;
            float2 o0 = make_float2(tf32rf(acc[mi][nt][0] * inv0),
                                    tf32rf(acc[mi][nt][1] * inv0));
            float2 o1 = make_float2(tf32rf(acc[mi][nt][2] * inv1),
                                    tf32rf(acc[mi][nt][3] * inv1));
            *(float2*)(o + (size_t)row0 * DM + col)       = o0;
            *(float2*)(o + (size_t)(row0 + 8) * DM + col) = o1;
        }
    }
}

// ---------------------------------------------------------------------------
// Launch: weight pre-round -> QKV GEMMs (fused, rounded out) -> attention
// (rounded out) -> output GEMM (raw fp32 out).
// ---------------------------------------------------------------------------
extern "C" void kernel_launch(void* const* d_in, const int* in_sizes, int n_in,
                              void* d_out, int out_size)
{
    const float* Q    = (const float*)d_in[0];
    const float* K    = (const float*)d_in[1];
    const float* V    = (const float*)d_in[2];
    const int*   mask = (const int*)  d_in[3];
    const float* Wq   = (const float*)d_in[4];
    const float* bq   = (const float*)d_in[5];
    const float* Wk   = (const float*)d_in[6];
    const float* bk   = (const float*)d_in[7];
    const float* Wv   = (const float*)d_in[8];
    const float* bv   = (const float*)d_in[9];
    const float* Wo   = (const float*)d_in[10];
    const float* bo   = (const float*)d_in[11];
    float* out = (float*)d_out;

    float *gq, *gk, *gv, *ga, *gwr;
    cudaGetSymbolAddress((void**)&gq,  g_q);
    cudaGetSymbolAddress((void**)&gk,  g_k);
    cudaGetSymbolAddress((void**)&gv,  g_v);
    cudaGetSymbolAddress((void**)&ga,  g_att);
    cudaGetSymbolAddress((void**)&gwr, g_wr);
    float* wrq = gwr + 0 * (size_t)DM * DM;
    float* wrk = gwr + 1 * (size_t)DM * DM;
    float* wrv = gwr + 2 * (size_t)DM * DM;
    float* wro = gwr + 3 * (size_t)DM * DM;

    cudaFuncSetAttribute(gemm_mma_k, cudaFuncAttributeMaxDynamicSharedMemorySize,
                         GEMM_SMEM);
    cudaFuncSetAttribute(attn_mma_k, cudaFuncAttributeMaxDynamicSharedMemorySize,
                         ATT_SMEM);

    round_w_k<<<1184, 256>>>(Wq, Wk, Wv, Wo, gwr);

    dim3 qkv_grid(DM / 128, MROWS / 128, 3);  // (8, 64, 3)
    dim3 out_grid(DM / 128, MROWS / 128, 1);  // (8, 64, 1)
    dim3 attn_grid(NB * NH, SEQ / 128);       // (64, 16)

    gemm_mma_k<<<qkv_grid, 128, GEMM_SMEM>>>(Q, K, V, wrq, wrk, wrv,
                                             bq, bk, bv, gq, gk, gv, 1);
    attn_mma_k<<<attn_grid, 128, ATT_SMEM>>>(gq, gk, gv, mask, ga);
    gemm_mma_k<<<out_grid, 128, GEMM_SMEM>>>(ga, ga, ga, wro, wro, wro,
                                             bo, bo, bo, out, out, out, 0);
}